// round 4
// baseline (speedup 1.0000x reference)
#include <cuda_runtime.h>
#include <cuda_bf16.h>
#include <cstdint>

// ---------------- problem constants ----------------
#define NUM_EXPERTS 64
#define DIM 2048
#define HIDDEN 1024
#define TOK_PER_E 256
#define TOTAL_TOKENS (NUM_EXPERTS * TOK_PER_E)

#define NTHREADS 256

// h scratch (fp32 tf32-rounded, 64 MB)
__device__ float g_h[(size_t)TOTAL_TOKENS * HIDDEN];

// ---------------- smem layout ----------------
#define A_PITCH_W 36
#define A_BYTES (128 * A_PITCH_W * 4)          // 18432
#define B64_PITCH_W 72
#define B64_BYTES (32 * B64_PITCH_W * 4)       // 9216
#define B128_PITCH_W 136
#define B128_BYTES (32 * B128_PITCH_W * 4)     // 17408

#define GU_STAGE (A_BYTES + 2 * B64_BYTES)     // 36864
#define DN_STAGE (A_BYTES + B128_BYTES)        // 35840
#define GU_SMEM (2 * GU_STAGE)                 // 73728
#define DN_SMEM (2 * DN_STAGE)                 // 71680

// ---------------- PTX helpers ----------------
__device__ __forceinline__ uint32_t smem_u32(const void* p) {
    uint32_t a;
    asm("{ .reg .u64 t; cvta.to.shared.u64 t, %1; cvt.u32.u64 %0, t; }" : "=r"(a) : "l"(p));
    return a;
}
__device__ __forceinline__ uint32_t tf32r(float v) {
    uint32_t o; asm("cvt.rna.tf32.f32 %0, %1;" : "=r"(o) : "f"(v)); return o;
}
__device__ __forceinline__ void cp_async16(uint32_t dst, const void* src) {
    asm volatile("cp.async.cg.shared.global [%0], [%1], 16;" :: "r"(dst), "l"(src));
}
__device__ __forceinline__ void cp_commit() {
    asm volatile("cp.async.commit_group;" ::: "memory");
}
template <int N>
__device__ __forceinline__ void cp_wait() {
    asm volatile("cp.async.wait_group %0;" :: "n"(N) : "memory");
}
__device__ __forceinline__ void mma_tf32(float d[4], const uint32_t a[4],
                                         uint32_t b0, uint32_t b1) {
    asm volatile(
        "mma.sync.aligned.m16n8k8.row.col.f32.tf32.tf32.f32 "
        "{%0,%1,%2,%3}, {%4,%5,%6,%7}, {%8,%9}, {%0,%1,%2,%3};"
        : "+f"(d[0]), "+f"(d[1]), "+f"(d[2]), "+f"(d[3])
        : "r"(a[0]), "r"(a[1]), "r"(a[2]), "r"(a[3]), "r"(b0), "r"(b1));
}

// in-place tf32 conversion of a contiguous float4 region
__device__ __forceinline__ void cvt_region(float4* p, int nchunks, int tid) {
    for (int i = tid; i < nchunks; i += NTHREADS) {
        float4 v = p[i];
        v.x = __uint_as_float(tf32r(v.x));
        v.y = __uint_as_float(tf32r(v.y));
        v.z = __uint_as_float(tf32r(v.z));
        v.w = __uint_as_float(tf32r(v.w));
        p[i] = v;
    }
}

// ================= fused gate/up + SiLU =================
// BM=128, BN=64 (per matrix), BK=32. 8 warps: wm=wid>>1 (4), wn=wid&1 (2).
__global__ __launch_bounds__(NTHREADS, 2)
void moe_gateup(const float* __restrict__ x, const float* __restrict__ w1,
                const float* __restrict__ w3, float* __restrict__ h)
{
    extern __shared__ char smem[];
    const int tid = threadIdx.x, lane = tid & 31, wid = tid >> 5;
    const int wm = wid >> 1, wn = wid & 1, g = lane >> 2, c = lane & 3;
    const int e = blockIdx.z, mt = blockIdx.y, nt = blockIdx.x;

    const float* xe  = x  + ((long long)e * TOK_PER_E + mt * 128) * DIM;
    const float* w1e = w1 + (long long)e * DIM * HIDDEN + nt * 64;
    const float* w3e = w3 + (long long)e * DIM * HIDDEN + nt * 64;

    auto load_stage = [&](int buf, int kt) {
        uint32_t sA = smem_u32(smem + buf * GU_STAGE);
#pragma unroll
        for (int j = 0; j < 4; j++) {
            int id = tid + 256 * j;
            int r = id >> 3, c4 = id & 7;
            cp_async16(sA + r * 144 + c4 * 16, xe + (long long)r * DIM + kt + c4 * 4);
        }
        uint32_t sB1 = sA + A_BYTES, sB3 = sB1 + B64_BYTES;
#pragma unroll
        for (int j = 0; j < 2; j++) {
            int id = tid + 256 * j;
            int k = id >> 4, c4 = id & 15;
            cp_async16(sB1 + k * 288 + c4 * 16, w1e + (long long)(kt + k) * HIDDEN + c4 * 4);
            cp_async16(sB3 + k * 288 + c4 * 16, w3e + (long long)(kt + k) * HIDDEN + c4 * 4);
        }
        cp_commit();
    };

    float accG[2][4][4] = {}, accU[2][4][4] = {};

    load_stage(0, 0);
    load_stage(1, 32);

    const int NIT = DIM / 32;  // 64
    for (int it = 0; it < NIT; ++it) {
        const int buf = it & 1;
        if (it == NIT - 1) cp_wait<0>(); else cp_wait<1>();
        __syncthreads();

        // one-shot tf32 conversion of the whole stage (2304 float4 = 9/thread)
        cvt_region((float4*)(smem + buf * GU_STAGE), GU_STAGE / 16, tid);
        __syncthreads();

        const uint32_t* As  = (const uint32_t*)(smem + buf * GU_STAGE);
        const uint32_t* B1s = As + 128 * A_PITCH_W;
        const uint32_t* B3s = B1s + 32 * B64_PITCH_W;

#pragma unroll
        for (int s = 0; s < 4; s++) {
            const int k0 = 8 * s + c;
            uint32_t a[2][4];
#pragma unroll
            for (int mi = 0; mi < 2; mi++) {
                const uint32_t* ap = As + (wm * 32 + mi * 16 + g) * A_PITCH_W + k0;
                a[mi][0] = ap[0];
                a[mi][1] = ap[8 * A_PITCH_W];
                a[mi][2] = ap[4];
                a[mi][3] = ap[8 * A_PITCH_W + 4];
            }
#pragma unroll
            for (int ni = 0; ni < 4; ni++) {
                const int nb = wn * 32 + ni * 8 + g;
                {
                    const uint32_t* bp = B1s + k0 * B64_PITCH_W + nb;
                    uint32_t b0 = bp[0], b1v = bp[4 * B64_PITCH_W];
                    mma_tf32(accG[0][ni], a[0], b0, b1v);
                    mma_tf32(accG[1][ni], a[1], b0, b1v);
                }
                {
                    const uint32_t* bp = B3s + k0 * B64_PITCH_W + nb;
                    uint32_t b0 = bp[0], b1v = bp[4 * B64_PITCH_W];
                    mma_tf32(accU[0][ni], a[0], b0, b1v);
                    mma_tf32(accU[1][ni], a[1], b0, b1v);
                }
            }
        }
        __syncthreads();
        if (it + 2 < NIT) load_stage(buf, (it + 2) * 32);
    }

    // epilogue: h = silu(gate) * up, stored tf32-rounded so moe_down skips cvt
    const int colbase = nt * 64 + wn * 32;
    const long long rowbase = (long long)e * TOK_PER_E + mt * 128 + wm * 32;
#pragma unroll
    for (int mi = 0; mi < 2; mi++) {
        const long long r0 = rowbase + mi * 16 + g;
#pragma unroll
        for (int ni = 0; ni < 4; ni++) {
            const int col = colbase + ni * 8 + 2 * c;
            float* p0 = h + r0 * HIDDEN + col;
            float* p1 = p0 + 8 * HIDDEN;
            float gv, uv; float2 o;
            gv = accG[mi][ni][0]; uv = accU[mi][ni][0];
            o.x = __uint_as_float(tf32r(gv / (1.f + __expf(-gv)) * uv));
            gv = accG[mi][ni][1]; uv = accU[mi][ni][1];
            o.y = __uint_as_float(tf32r(gv / (1.f + __expf(-gv)) * uv));
            *(float2*)p0 = o;
            gv = accG[mi][ni][2]; uv = accU[mi][ni][2];
            o.x = __uint_as_float(tf32r(gv / (1.f + __expf(-gv)) * uv));
            gv = accG[mi][ni][3]; uv = accU[mi][ni][3];
            o.y = __uint_as_float(tf32r(gv / (1.f + __expf(-gv)) * uv));
            *(float2*)p1 = o;
        }
    }
}

// ================= down-projection =================
// BM=128, BN=128, BK=32. Warp tile 32 x 64.
__global__ __launch_bounds__(NTHREADS, 2)
void moe_down(const float* __restrict__ h, const float* __restrict__ w2,
              float* __restrict__ out)
{
    extern __shared__ char smem[];
    const int tid = threadIdx.x, lane = tid & 31, wid = tid >> 5;
    const int wm = wid >> 1, wn = wid & 1, g = lane >> 2, c = lane & 3;
    const int e = blockIdx.z, mt = blockIdx.y, nt = blockIdx.x;

    const float* he  = h  + ((long long)e * TOK_PER_E + mt * 128) * HIDDEN;
    const float* w2e = w2 + (long long)e * HIDDEN * DIM + nt * 128;

    auto load_stage = [&](int buf, int kt) {
        uint32_t sA = smem_u32(smem + buf * DN_STAGE);
#pragma unroll
        for (int j = 0; j < 4; j++) {
            int id = tid + 256 * j;
            int r = id >> 3, c4 = id & 7;
            cp_async16(sA + r * 144 + c4 * 16, he + (long long)r * HIDDEN + kt + c4 * 4);
        }
        uint32_t sB = sA + A_BYTES;
#pragma unroll
        for (int j = 0; j < 4; j++) {
            int id = tid + 256 * j;
            int k = id >> 5, c4 = id & 31;
            cp_async16(sB + k * 544 + c4 * 16, w2e + (long long)(kt + k) * DIM + c4 * 4);
        }
        cp_commit();
    };

    float acc[2][8][4] = {};

    load_stage(0, 0);
    load_stage(1, 32);

    const int NIT = HIDDEN / 32;  // 32
    for (int it = 0; it < NIT; ++it) {
        const int buf = it & 1;
        if (it == NIT - 1) cp_wait<0>(); else cp_wait<1>();
        __syncthreads();

        // A (= h) is already tf32-rounded; convert only the B (w2) region
        cvt_region((float4*)(smem + buf * DN_STAGE + A_BYTES), B128_BYTES / 16, tid);
        __syncthreads();

        const uint32_t* As = (const uint32_t*)(smem + buf * DN_STAGE);
        const uint32_t* Bs = As + 128 * A_PITCH_W;

#pragma unroll
        for (int s = 0; s < 4; s++) {
            const int k0 = 8 * s + c;
            uint32_t a[2][4];
#pragma unroll
            for (int mi = 0; mi < 2; mi++) {
                const uint32_t* ap = As + (wm * 32 + mi * 16 + g) * A_PITCH_W + k0;
                a[mi][0] = ap[0];
                a[mi][1] = ap[8 * A_PITCH_W];
                a[mi][2] = ap[4];
                a[mi][3] = ap[8 * A_PITCH_W + 4];
            }
#pragma unroll
            for (int ni = 0; ni < 8; ni++) {
                const uint32_t* bp = Bs + k0 * B128_PITCH_W + wn * 64 + ni * 8 + g;
                uint32_t b0 = bp[0], b1v = bp[4 * B128_PITCH_W];
                mma_tf32(acc[0][ni], a[0], b0, b1v);
                mma_tf32(acc[1][ni], a[1], b0, b1v);
            }
        }
        __syncthreads();
        if (it + 2 < NIT) load_stage(buf, (it + 2) * 32);
    }

    const int colbase = nt * 128 + wn * 64;
    const long long rowbase = (long long)e * TOK_PER_E + mt * 128 + wm * 32;
#pragma unroll
    for (int mi = 0; mi < 2; mi++) {
        const long long r0 = rowbase + mi * 16 + g;
#pragma unroll
        for (int ni = 0; ni < 8; ni++) {
            const int col = colbase + ni * 8 + 2 * c;
            float* p0 = out + r0 * DIM + col;
            float* p1 = p0 + 8 * DIM;
            *(float2*)p0 = make_float2(acc[mi][ni][0], acc[mi][ni][1]);
            *(float2*)p1 = make_float2(acc[mi][ni][2], acc[mi][ni][3]);
        }
    }
}

// ================= launch =================
extern "C" void kernel_launch(void* const* d_in, const int* in_sizes, int n_in,
                              void* d_out, int out_size)
{
    const float* x  = (const float*)d_in[0];
    const float* w1 = (const float*)d_in[1];
    const float* w2 = (const float*)d_in[2];
    const float* w3 = (const float*)d_in[3];
    float* out = (float*)d_out;

    float* h = nullptr;
    cudaGetSymbolAddress((void**)&h, g_h);

    static bool attr_done = false;
    if (!attr_done) {
        cudaFuncSetAttribute(moe_gateup, cudaFuncAttributeMaxDynamicSharedMemorySize, GU_SMEM);
        cudaFuncSetAttribute(moe_down, cudaFuncAttributeMaxDynamicSharedMemorySize, DN_SMEM);
        attr_done = true;
    }

    {
        dim3 grid(HIDDEN / 64, TOK_PER_E / 128, NUM_EXPERTS);  // (16, 2, 64)
        moe_gateup<<<grid, NTHREADS, GU_SMEM>>>(x, w1, w3, h);
    }
    {
        dim3 grid(DIM / 128, TOK_PER_E / 128, NUM_EXPERTS);    // (16, 2, 64)
        moe_down<<<grid, NTHREADS, DN_SMEM>>>(h, w2, out);
    }
}

// round 5
// speedup vs baseline: 1.0270x; 1.0270x over previous
#include <cuda_runtime.h>
#include <cuda_bf16.h>
#include <cstdint>

// ---------------- problem constants ----------------
#define NUM_EXPERTS 64
#define DIM 2048
#define HIDDEN 1024
#define TOK_PER_E 256
#define TOTAL_TOKENS (NUM_EXPERTS * TOK_PER_E)

#define NTHREADS 256

// scratch: h (tf32-rounded fp32, 64 MB) and fragment-packed x (128 MB)
__device__ float g_h[(size_t)TOTAL_TOKENS * HIDDEN];
__device__ float g_xp[(size_t)TOTAL_TOKENS * DIM];

// ---------------- smem layout ----------------
// gateup stage: A packed 16384 | B1 packed 8192 | B3 packed 8192 = 32768
#define GU_STAGE 32768
#define GU_SMEM (2 * GU_STAGE)
// down stage: A row-major pitch 36w (18432) | B packed 16384 = 34816
#define A_PITCH_W 36
#define A_BYTES (128 * A_PITCH_W * 4)
#define DN_STAGE (A_BYTES + 16384)
#define DN_SMEM (2 * DN_STAGE)

// ---------------- PTX helpers ----------------
__device__ __forceinline__ uint32_t smem_u32(const void* p) {
    uint32_t a;
    asm("{ .reg .u64 t; cvta.to.shared.u64 t, %1; cvt.u32.u64 %0, t; }" : "=r"(a) : "l"(p));
    return a;
}
__device__ __forceinline__ uint32_t tf32r(float v) {
    uint32_t o; asm("cvt.rna.tf32.f32 %0, %1;" : "=r"(o) : "f"(v)); return o;
}
__device__ __forceinline__ void cp_async16(uint32_t dst, const void* src) {
    asm volatile("cp.async.cg.shared.global [%0], [%1], 16;" :: "r"(dst), "l"(src));
}
__device__ __forceinline__ void cp_commit() {
    asm volatile("cp.async.commit_group;" ::: "memory");
}
template <int N>
__device__ __forceinline__ void cp_wait() {
    asm volatile("cp.async.wait_group %0;" :: "n"(N) : "memory");
}
__device__ __forceinline__ void mma_tf32(float d[4], const uint32_t a[4],
                                         uint32_t b0, uint32_t b1) {
    asm volatile(
        "mma.sync.aligned.m16n8k8.row.col.f32.tf32.tf32.f32 "
        "{%0,%1,%2,%3}, {%4,%5,%6,%7}, {%8,%9}, {%0,%1,%2,%3};"
        : "+f"(d[0]), "+f"(d[1]), "+f"(d[2]), "+f"(d[3])
        : "r"(a[0]), "r"(a[1]), "r"(a[2]), "r"(a[3]), "r"(b0), "r"(b1));
}

// ================= x pre-pass: round to tf32 + fragment-pack =================
// frag layout per (e, mt, stage-it): 32 frags (mt16 0..7, s 0..3) x 32 lanes x float4
// lane(g,c) float4 = { x[g][8s+c], x[g+8][8s+c], x[g][8s+c+4], x[g+8][8s+c+4] }
__global__ void xpack_kernel(const float* __restrict__ x, float* __restrict__ xp)
{
    const int it = blockIdx.x, mt = blockIdx.y, e = blockIdx.z, tid = threadIdx.x;
    const float* src = x + ((long long)e * TOK_PER_E + mt * 128) * DIM + it * 32;
    float4* dst = (float4*)(xp + ((long long)(e * 2 + mt) * 64 + it) * 4096);
#pragma unroll
    for (int j = 0; j < 4; j++) {
        int fl = tid + 256 * j;
        int fA = fl >> 5, lane = fl & 31;
        int mt16 = fA >> 2, s = fA & 3, g = lane >> 2, c = lane & 3;
        const float* p = src + (long long)(mt16 * 16 + g) * DIM + s * 8 + c;
        float4 v;
        v.x = __uint_as_float(tf32r(p[0]));
        v.y = __uint_as_float(tf32r(p[8 * DIM]));
        v.z = __uint_as_float(tf32r(p[4]));
        v.w = __uint_as_float(tf32r(p[8 * DIM + 4]));
        dst[fl] = v;
    }
}

// ================= fused gate/up + SiLU =================
// BM=128, BN=64 per matrix, BK=32. 8 warps: wm (4) x wn (2), warp tile 32x32 per matrix.
__global__ __launch_bounds__(NTHREADS, 2)
void moe_gateup(const float* __restrict__ xp, const float* __restrict__ w1,
                const float* __restrict__ w3, float* __restrict__ h)
{
    extern __shared__ char smem[];
    const int tid = threadIdx.x, lane = tid & 31, wid = tid >> 5;
    const int wm = wid >> 1, wn = wid & 1, g = lane >> 2, c = lane & 3;
    const int e = blockIdx.z, mt = blockIdx.y, nt = blockIdx.x;

    const float4* xpe = (const float4*)(xp + (long long)(e * 2 + mt) * 64 * 4096);
    const float* w1e = w1 + (long long)e * DIM * HIDDEN + nt * 64;
    const float* w3e = w3 + (long long)e * DIM * HIDDEN + nt * 64;

    // B staging regs (held across compute)
    float2 v1[4], v3[4];

    auto ldgB = [&](int kt) {
#pragma unroll
        for (int j = 0; j < 4; j++) {
            int fl = tid + 256 * j;
            int fB = fl >> 5, ln = fl & 31;
            int n8 = fB >> 2, s = fB & 3, gg = ln >> 2, cc = ln & 3;
            const float* p1 = w1e + (long long)(kt + 8 * s + cc) * HIDDEN + n8 * 8 + gg;
            v1[j].x = p1[0]; v1[j].y = p1[4 * HIDDEN];
            const float* p3 = w3e + (long long)(kt + 8 * s + cc) * HIDDEN + n8 * 8 + gg;
            v3[j].x = p3[0]; v3[j].y = p3[4 * HIDDEN];
        }
    };
    auto stsB = [&](int buf) {
        float2* d1 = (float2*)(smem + buf * GU_STAGE + 16384);
        float2* d3 = d1 + 1024;
#pragma unroll
        for (int j = 0; j < 4; j++) {
            int fl = tid + 256 * j;
            float2 a, b;
            a.x = __uint_as_float(tf32r(v1[j].x)); a.y = __uint_as_float(tf32r(v1[j].y));
            b.x = __uint_as_float(tf32r(v3[j].x)); b.y = __uint_as_float(tf32r(v3[j].y));
            d1[fl] = a; d3[fl] = b;
        }
    };
    auto ldA = [&](int stage, int buf) {
        uint32_t sA = smem_u32(smem + buf * GU_STAGE);
        const float4* src = xpe + (long long)stage * 1024;
#pragma unroll
        for (int j = 0; j < 4; j++) {
            int idx = tid + 256 * j;
            cp_async16(sA + idx * 16, src + idx);
        }
        cp_commit();
    };

    float accG[2][4][4] = {}, accU[2][4][4] = {};

    // prologue
    ldA(0, 0);
    ldgB(0);
    ldA(1, 1);
    stsB(0);
    ldgB(32);
    cp_wait<1>();
    __syncthreads();

    const int NIT = DIM / 32;  // 64
    for (int it = 0; it < NIT; ++it) {
        const int b = it & 1;
        const uint4* Ap = (const uint4*)(smem + b * GU_STAGE);
        const float2* B1p = (const float2*)(smem + b * GU_STAGE + 16384);
        const float2* B3p = B1p + 1024;
#pragma unroll
        for (int s = 0; s < 4; s++) {
            uint32_t A0[4], A1[4];
            {
                uint4 t0 = Ap[((2 * wm + 0) * 4 + s) * 32 + lane];
                uint4 t1 = Ap[((2 * wm + 1) * 4 + s) * 32 + lane];
                A0[0] = t0.x; A0[1] = t0.y; A0[2] = t0.z; A0[3] = t0.w;
                A1[0] = t1.x; A1[1] = t1.y; A1[2] = t1.z; A1[3] = t1.w;
            }
#pragma unroll
            for (int ni = 0; ni < 4; ni++) {
                const int fi = ((wn * 4 + ni) * 4 + s) * 32 + lane;
                float2 bb = B1p[fi];
                mma_tf32(accG[0][ni], A0, __float_as_uint(bb.x), __float_as_uint(bb.y));
                mma_tf32(accG[1][ni], A1, __float_as_uint(bb.x), __float_as_uint(bb.y));
                float2 bc = B3p[fi];
                mma_tf32(accU[0][ni], A0, __float_as_uint(bc.x), __float_as_uint(bc.y));
                mma_tf32(accU[1][ni], A1, __float_as_uint(bc.x), __float_as_uint(bc.y));
            }
        }
        if (it + 1 < NIT) {
            stsB(1 - b);
            cp_wait<0>();
            __syncthreads();
            if (it + 2 < NIT) { ldA(it + 2, b); ldgB((it + 2) * 32); }
        }
    }

    // epilogue: h = silu(gate) * up, tf32-rounded
    const int colbase = nt * 64 + wn * 32;
    const long long rowbase = (long long)e * TOK_PER_E + mt * 128 + wm * 32;
#pragma unroll
    for (int mi = 0; mi < 2; mi++) {
        const long long r0 = rowbase + mi * 16 + g;
#pragma unroll
        for (int ni = 0; ni < 4; ni++) {
            const int col = colbase + ni * 8 + 2 * c;
            float* p0 = h + r0 * HIDDEN + col;
            float* p1 = p0 + 8 * HIDDEN;
            float gv, uv; float2 o;
            gv = accG[mi][ni][0]; uv = accU[mi][ni][0];
            o.x = __uint_as_float(tf32r(gv / (1.f + __expf(-gv)) * uv));
            gv = accG[mi][ni][1]; uv = accU[mi][ni][1];
            o.y = __uint_as_float(tf32r(gv / (1.f + __expf(-gv)) * uv));
            *(float2*)p0 = o;
            gv = accG[mi][ni][2]; uv = accU[mi][ni][2];
            o.x = __uint_as_float(tf32r(gv / (1.f + __expf(-gv)) * uv));
            gv = accG[mi][ni][3]; uv = accU[mi][ni][3];
            o.y = __uint_as_float(tf32r(gv / (1.f + __expf(-gv)) * uv));
            *(float2*)p1 = o;
        }
    }
}

// ================= down-projection =================
// BM=128, BN=128, BK=32. Warp tile 32x64.
__global__ __launch_bounds__(NTHREADS, 2)
void moe_down(const float* __restrict__ h, const float* __restrict__ w2,
              float* __restrict__ out)
{
    extern __shared__ char smem[];
    const int tid = threadIdx.x, lane = tid & 31, wid = tid >> 5;
    const int wm = wid >> 1, wn = wid & 1, g = lane >> 2, c = lane & 3;
    const int e = blockIdx.z, mt = blockIdx.y, nt = blockIdx.x;

    const float* he  = h  + ((long long)e * TOK_PER_E + mt * 128) * HIDDEN;
    const float* w2e = w2 + (long long)e * HIDDEN * DIM + nt * 128;

    float2 v[8];

    auto ldgB = [&](int kt) {
#pragma unroll
        for (int j = 0; j < 8; j++) {
            int fl = tid + 256 * j;
            int fB = fl >> 5, ln = fl & 31;
            int n8 = fB >> 2, s = fB & 3, gg = ln >> 2, cc = ln & 3;
            const float* p = w2e + (long long)(kt + 8 * s + cc) * DIM + n8 * 8 + gg;
            v[j].x = p[0]; v[j].y = p[4 * DIM];
        }
    };
    auto stsB = [&](int buf) {
        float2* d = (float2*)(smem + buf * DN_STAGE + A_BYTES);
#pragma unroll
        for (int j = 0; j < 8; j++) {
            int fl = tid + 256 * j;
            float2 a;
            a.x = __uint_as_float(tf32r(v[j].x));
            a.y = __uint_as_float(tf32r(v[j].y));
            d[fl] = a;
        }
    };
    auto ldA = [&](int stage, int buf) {
        uint32_t sA = smem_u32(smem + buf * DN_STAGE);
#pragma unroll
        for (int j = 0; j < 4; j++) {
            int id = tid + 256 * j;
            int r = id >> 3, c4 = id & 7;
            cp_async16(sA + r * 144 + c4 * 16,
                       he + (long long)r * HIDDEN + stage * 32 + c4 * 4);
        }
        cp_commit();
    };

    float acc[2][8][4] = {};

    // prologue
    ldA(0, 0);
    ldgB(0);
    ldA(1, 1);
    stsB(0);
    ldgB(32);
    cp_wait<1>();
    __syncthreads();

    const int NIT = HIDDEN / 32;  // 32
    for (int it = 0; it < NIT; ++it) {
        const int b = it & 1;
        const uint32_t* As = (const uint32_t*)(smem + b * DN_STAGE);
        const float2* Bp = (const float2*)(smem + b * DN_STAGE + A_BYTES);
#pragma unroll
        for (int s = 0; s < 4; s++) {
            const int k0 = 8 * s + c;
            uint32_t a[2][4];
#pragma unroll
            for (int mi = 0; mi < 2; mi++) {
                const uint32_t* ap = As + (wm * 32 + mi * 16 + g) * A_PITCH_W + k0;
                a[mi][0] = ap[0];
                a[mi][1] = ap[8 * A_PITCH_W];
                a[mi][2] = ap[4];
                a[mi][3] = ap[8 * A_PITCH_W + 4];
            }
#pragma unroll
            for (int ni = 0; ni < 8; ni++) {
                float2 bb = Bp[((wn * 8 + ni) * 4 + s) * 32 + lane];
                mma_tf32(acc[0][ni], a[0], __float_as_uint(bb.x), __float_as_uint(bb.y));
                mma_tf32(acc[1][ni], a[1], __float_as_uint(bb.x), __float_as_uint(bb.y));
            }
        }
        if (it + 1 < NIT) {
            stsB(1 - b);
            cp_wait<0>();
            __syncthreads();
            if (it + 2 < NIT) { ldA(it + 2, b); ldgB((it + 2) * 32); }
        }
    }

    const int colbase = nt * 128 + wn * 64;
    const long long rowbase = (long long)e * TOK_PER_E + mt * 128 + wm * 32;
#pragma unroll
    for (int mi = 0; mi < 2; mi++) {
        const long long r0 = rowbase + mi * 16 + g;
#pragma unroll
        for (int ni = 0; ni < 8; ni++) {
            const int col = colbase + ni * 8 + 2 * c;
            float* p0 = out + r0 * DIM + col;
            float* p1 = p0 + 8 * DIM;
            *(float2*)p0 = make_float2(acc[mi][ni][0], acc[mi][ni][1]);
            *(float2*)p1 = make_float2(acc[mi][ni][2], acc[mi][ni][3]);
        }
    }
}

// ================= launch =================
extern "C" void kernel_launch(void* const* d_in, const int* in_sizes, int n_in,
                              void* d_out, int out_size)
{
    const float* x  = (const float*)d_in[0];
    const float* w1 = (const float*)d_in[1];
    const float* w2 = (const float*)d_in[2];
    const float* w3 = (const float*)d_in[3];
    float* out = (float*)d_out;

    float* h = nullptr;
    float* xp = nullptr;
    cudaGetSymbolAddress((void**)&h, g_h);
    cudaGetSymbolAddress((void**)&xp, g_xp);

    static bool attr_done = false;
    if (!attr_done) {
        cudaFuncSetAttribute(moe_gateup, cudaFuncAttributeMaxDynamicSharedMemorySize, GU_SMEM);
        cudaFuncSetAttribute(moe_down, cudaFuncAttributeMaxDynamicSharedMemorySize, DN_SMEM);
        attr_done = true;
    }

    {
        dim3 grid(DIM / 32, TOK_PER_E / 128, NUM_EXPERTS);     // (64, 2, 64)
        xpack_kernel<<<grid, NTHREADS>>>(x, xp);
    }
    {
        dim3 grid(HIDDEN / 64, TOK_PER_E / 128, NUM_EXPERTS);  // (16, 2, 64)
        moe_gateup<<<grid, NTHREADS, GU_SMEM>>>(xp, w1, w3, h);
    }
    {
        dim3 grid(DIM / 128, TOK_PER_E / 128, NUM_EXPERTS);    // (16, 2, 64)
        moe_down<<<grid, NTHREADS, DN_SMEM>>>(h, w2, out);
    }
}

// round 6
// speedup vs baseline: 1.2087x; 1.1769x over previous
#include <cuda_runtime.h>
#include <cuda_bf16.h>
#include <cstdint>

// ---------------- problem constants ----------------
#define NUM_EXPERTS 64
#define DIM 2048
#define HIDDEN 1024
#define TOK_PER_E 256
#define TOTAL_TOKENS (NUM_EXPERTS * TOK_PER_E)

#define NTHREADS 256

// h scratch (tf32-rounded fp32, 64 MB)
__device__ float g_h[(size_t)TOTAL_TOKENS * HIDDEN];

// ---------------- smem layout ----------------
#define A_PITCH_W 36
#define A_BYTES (128 * A_PITCH_W * 4)          // 18432
#define B64_PITCH_W 72
#define B64_BYTES (32 * B64_PITCH_W * 4)       // 9216
#define B128_PITCH_W 136
#define B128_BYTES (32 * B128_PITCH_W * 4)     // 17408

// A: 3-stage ring.  B: 2-stage (regs act as 3rd stage).
#define GU_B_BASE (3 * A_BYTES)
#define GU_B_STAGE (2 * B64_BYTES)
#define GU_SMEM (3 * A_BYTES + 2 * GU_B_STAGE)   // 92160
#define DN_B_BASE (3 * A_BYTES)
#define DN_SMEM (3 * A_BYTES + 2 * B128_BYTES)   // 90112

// ---------------- PTX helpers ----------------
__device__ __forceinline__ uint32_t smem_u32(const void* p) {
    uint32_t a;
    asm("{ .reg .u64 t; cvta.to.shared.u64 t, %1; cvt.u32.u64 %0, t; }" : "=r"(a) : "l"(p));
    return a;
}
__device__ __forceinline__ uint32_t tf32r(float v) {
    uint32_t o; asm("cvt.rna.tf32.f32 %0, %1;" : "=r"(o) : "f"(v)); return o;
}
__device__ __forceinline__ void cp_async16(uint32_t dst, const void* src) {
    asm volatile("cp.async.cg.shared.global [%0], [%1], 16;" :: "r"(dst), "l"(src));
}
__device__ __forceinline__ void cp_commit() {
    asm volatile("cp.async.commit_group;" ::: "memory");
}
template <int N>
__device__ __forceinline__ void cp_wait() {
    asm volatile("cp.async.wait_group %0;" :: "n"(N) : "memory");
}
__device__ __forceinline__ void mma_tf32(float d[4], const uint32_t a[4],
                                         uint32_t b0, uint32_t b1) {
    asm volatile(
        "mma.sync.aligned.m16n8k8.row.col.f32.tf32.tf32.f32 "
        "{%0,%1,%2,%3}, {%4,%5,%6,%7}, {%8,%9}, {%0,%1,%2,%3};"
        : "+f"(d[0]), "+f"(d[1]), "+f"(d[2]), "+f"(d[3])
        : "r"(a[0]), "r"(a[1]), "r"(a[2]), "r"(a[3]), "r"(b0), "r"(b1));
}
__device__ __forceinline__ float4 cvt4(float4 v) {
    v.x = __uint_as_float(tf32r(v.x));
    v.y = __uint_as_float(tf32r(v.y));
    v.z = __uint_as_float(tf32r(v.z));
    v.w = __uint_as_float(tf32r(v.w));
    return v;
}

// ================= fused gate/up + SiLU =================
// BM=128, BN=64 per matrix, BK=32. 8 warps: wm(4) x wn(2), warp tile 32x32 per matrix.
__global__ __launch_bounds__(NTHREADS, 2)
void moe_gateup(const float* __restrict__ x, const float* __restrict__ w1,
                const float* __restrict__ w3, float* __restrict__ h)
{
    extern __shared__ char smem[];
    const int tid = threadIdx.x, lane = tid & 31, wid = tid >> 5;
    const int wm = wid >> 1, wn = wid & 1, g = lane >> 2, c = lane & 3;
    const int e = blockIdx.z, mt = blockIdx.y, nt = blockIdx.x;

    const float* xe  = x  + ((long long)e * TOK_PER_E + mt * 128) * DIM;
    const float* w1e = w1 + (long long)e * DIM * HIDDEN + nt * 64;
    const float* w3e = w3 + (long long)e * DIM * HIDDEN + nt * 64;

    float4 v1[2], v3[2];  // B staging registers

    auto ldgB = [&](int kt) {
#pragma unroll
        for (int j = 0; j < 2; j++) {
            int id = tid + 256 * j;
            int k = id >> 4, c4 = id & 15;
            v1[j] = *(const float4*)(w1e + (long long)(kt + k) * HIDDEN + c4 * 4);
            v3[j] = *(const float4*)(w3e + (long long)(kt + k) * HIDDEN + c4 * 4);
        }
    };
    auto stsB = [&](int buf) {
        char* base = smem + GU_B_BASE + buf * GU_B_STAGE;
#pragma unroll
        for (int j = 0; j < 2; j++) {
            int id = tid + 256 * j;
            int k = id >> 4, c4 = id & 15;
            *(float4*)(base + k * 288 + c4 * 16) = cvt4(v1[j]);
            *(float4*)(base + B64_BYTES + k * 288 + c4 * 16) = cvt4(v3[j]);
        }
    };
    auto ldA = [&](int stage, int buf) {
        uint32_t sA = smem_u32(smem) + buf * A_BYTES;
#pragma unroll
        for (int j = 0; j < 4; j++) {
            int id = tid + 256 * j;
            int r = id >> 3, c4 = id & 7;
            cp_async16(sA + r * 144 + c4 * 16,
                       xe + (long long)r * DIM + stage * 32 + c4 * 4);
        }
        cp_commit();
    };

    float accG[2][4][4] = {}, accU[2][4][4] = {};

    // prologue: A stages 0,1 in flight; B stage0 in smem, stage1 in regs
    ldgB(0);
    ldA(0, 0);
    ldA(1, 1);
    stsB(0);
    ldgB(32);
    cp_wait<1>();
    __syncthreads();

    const int NIT = DIM / 32;  // 64
    int a3 = 0, a3n = 2;       // current A buf, buf for stage it+2
    for (int it = 0; it < NIT; ++it) {
        const int b = it & 1;
        if (it + 2 < NIT) ldA(it + 2, a3n);

        const uint32_t* As  = (const uint32_t*)(smem + a3 * A_BYTES);
        const uint32_t* B1s = (const uint32_t*)(smem + GU_B_BASE + b * GU_B_STAGE);
        const uint32_t* B3s = B1s + 32 * B64_PITCH_W;

#pragma unroll
        for (int s = 0; s < 4; s++) {
            const int k0 = 8 * s + c;
            uint32_t a[2][4];
#pragma unroll
            for (int mi = 0; mi < 2; mi++) {
                const float* ap = (const float*)(As + (wm * 32 + mi * 16 + g) * A_PITCH_W + k0);
                a[mi][0] = tf32r(ap[0]);
                a[mi][1] = tf32r(ap[8 * A_PITCH_W]);
                a[mi][2] = tf32r(ap[4]);
                a[mi][3] = tf32r(ap[8 * A_PITCH_W + 4]);
            }
#pragma unroll
            for (int ni = 0; ni < 4; ni++) {
                const int nb = wn * 32 + ni * 8 + g;
                {
                    const uint32_t* bp = B1s + k0 * B64_PITCH_W + nb;
                    uint32_t b0 = bp[0], b1v = bp[4 * B64_PITCH_W];
                    mma_tf32(accG[0][ni], a[0], b0, b1v);
                    mma_tf32(accG[1][ni], a[1], b0, b1v);
                }
                {
                    const uint32_t* bp = B3s + k0 * B64_PITCH_W + nb;
                    uint32_t b0 = bp[0], b1v = bp[4 * B64_PITCH_W];
                    mma_tf32(accU[0][ni], a[0], b0, b1v);
                    mma_tf32(accU[1][ni], a[1], b0, b1v);
                }
            }
        }
        if (it + 1 < NIT) stsB(1 - b);
        if (it + 2 < NIT) { ldgB((it + 2) * 32); cp_wait<1>(); }
        else cp_wait<0>();
        __syncthreads();
        a3 = (a3 == 2) ? 0 : a3 + 1;
        a3n = (a3n == 2) ? 0 : a3n + 1;
    }

    // epilogue: h = silu(gate) * up, tf32-rounded (down kernel skips A cvt)
    const int colbase = nt * 64 + wn * 32;
    const long long rowbase = (long long)e * TOK_PER_E + mt * 128 + wm * 32;
#pragma unroll
    for (int mi = 0; mi < 2; mi++) {
        const long long r0 = rowbase + mi * 16 + g;
#pragma unroll
        for (int ni = 0; ni < 4; ni++) {
            const int col = colbase + ni * 8 + 2 * c;
            float* p0 = h + r0 * HIDDEN + col;
            float* p1 = p0 + 8 * HIDDEN;
            float gv, uv; float2 o;
            gv = accG[mi][ni][0]; uv = accU[mi][ni][0];
            o.x = __uint_as_float(tf32r(gv / (1.f + __expf(-gv)) * uv));
            gv = accG[mi][ni][1]; uv = accU[mi][ni][1];
            o.y = __uint_as_float(tf32r(gv / (1.f + __expf(-gv)) * uv));
            *(float2*)p0 = o;
            gv = accG[mi][ni][2]; uv = accU[mi][ni][2];
            o.x = __uint_as_float(tf32r(gv / (1.f + __expf(-gv)) * uv));
            gv = accG[mi][ni][3]; uv = accU[mi][ni][3];
            o.y = __uint_as_float(tf32r(gv / (1.f + __expf(-gv)) * uv));
            *(float2*)p1 = o;
        }
    }
}

// ================= down-projection =================
// BM=128, BN=128, BK=32. Warp tile 32x64.
__global__ __launch_bounds__(NTHREADS, 2)
void moe_down(const float* __restrict__ h, const float* __restrict__ w2,
              float* __restrict__ out)
{
    extern __shared__ char smem[];
    const int tid = threadIdx.x, lane = tid & 31, wid = tid >> 5;
    const int wm = wid >> 1, wn = wid & 1, g = lane >> 2, c = lane & 3;
    const int e = blockIdx.z, mt = blockIdx.y, nt = blockIdx.x;

    const float* he  = h  + ((long long)e * TOK_PER_E + mt * 128) * HIDDEN;
    const float* w2e = w2 + (long long)e * HIDDEN * DIM + nt * 128;

    float4 v[4];  // B staging registers

    auto ldgB = [&](int kt) {
#pragma unroll
        for (int j = 0; j < 4; j++) {
            int id = tid + 256 * j;
            int k = id >> 5, c4 = id & 31;
            v[j] = *(const float4*)(w2e + (long long)(kt + k) * DIM + c4 * 4);
        }
    };
    auto stsB = [&](int buf) {
        char* base = smem + DN_B_BASE + buf * B128_BYTES;
#pragma unroll
        for (int j = 0; j < 4; j++) {
            int id = tid + 256 * j;
            int k = id >> 5, c4 = id & 31;
            *(float4*)(base + k * 544 + c4 * 16) = cvt4(v[j]);
        }
    };
    auto ldA = [&](int stage, int buf) {
        uint32_t sA = smem_u32(smem) + buf * A_BYTES;
#pragma unroll
        for (int j = 0; j < 4; j++) {
            int id = tid + 256 * j;
            int r = id >> 3, c4 = id & 7;
            cp_async16(sA + r * 144 + c4 * 16,
                       he + (long long)r * HIDDEN + stage * 32 + c4 * 4);
        }
        cp_commit();
    };

    float acc[2][8][4] = {};

    ldgB(0);
    ldA(0, 0);
    ldA(1, 1);
    stsB(0);
    ldgB(32);
    cp_wait<1>();
    __syncthreads();

    const int NIT = HIDDEN / 32;  // 32
    int a3 = 0, a3n = 2;
    for (int it = 0; it < NIT; ++it) {
        const int b = it & 1;
        if (it + 2 < NIT) ldA(it + 2, a3n);

        const uint32_t* As = (const uint32_t*)(smem + a3 * A_BYTES);
        const uint32_t* Bs = (const uint32_t*)(smem + DN_B_BASE + b * B128_BYTES);

#pragma unroll
        for (int s = 0; s < 4; s++) {
            const int k0 = 8 * s + c;
            uint32_t a[2][4];
#pragma unroll
            for (int mi = 0; mi < 2; mi++) {
                const uint32_t* ap = As + (wm * 32 + mi * 16 + g) * A_PITCH_W + k0;
                a[mi][0] = ap[0];               // h pre-rounded: no cvt
                a[mi][1] = ap[8 * A_PITCH_W];
                a[mi][2] = ap[4];
                a[mi][3] = ap[8 * A_PITCH_W + 4];
            }
#pragma unroll
            for (int ni = 0; ni < 8; ni++) {
                const uint32_t* bp = Bs + k0 * B128_PITCH_W + wn * 64 + ni * 8 + g;
                uint32_t b0 = bp[0], b1v = bp[4 * B128_PITCH_W];
                mma_tf32(acc[0][ni], a[0], b0, b1v);
                mma_tf32(acc[1][ni], a[1], b0, b1v);
            }
        }
        if (it + 1 < NIT) stsB(1 - b);
        if (it + 2 < NIT) { ldgB((it + 2) * 32); cp_wait<1>(); }
        else cp_wait<0>();
        __syncthreads();
        a3 = (a3 == 2) ? 0 : a3 + 1;
        a3n = (a3n == 2) ? 0 : a3n + 1;
    }

    const int colbase = nt * 128 + wn * 64;
    const long long rowbase = (long long)e * TOK_PER_E + mt * 128 + wm * 32;
#pragma unroll
    for (int mi = 0; mi < 2; mi++) {
        const long long r0 = rowbase + mi * 16 + g;
#pragma unroll
        for (int ni = 0; ni < 8; ni++) {
            const int col = colbase + ni * 8 + 2 * c;
            float* p0 = out + r0 * DIM + col;
            float* p1 = p0 + 8 * DIM;
            *(float2*)p0 = make_float2(acc[mi][ni][0], acc[mi][ni][1]);
            *(float2*)p1 = make_float2(acc[mi][ni][2], acc[mi][ni][3]);
        }
    }
}

// ================= launch =================
extern "C" void kernel_launch(void* const* d_in, const int* in_sizes, int n_in,
                              void* d_out, int out_size)
{
    const float* x  = (const float*)d_in[0];
    const float* w1 = (const float*)d_in[1];
    const float* w2 = (const float*)d_in[2];
    const float* w3 = (const float*)d_in[3];
    float* out = (float*)d_out;

    float* h = nullptr;
    cudaGetSymbolAddress((void**)&h, g_h);

    static bool attr_done = false;
    if (!attr_done) {
        cudaFuncSetAttribute(moe_gateup, cudaFuncAttributeMaxDynamicSharedMemorySize, GU_SMEM);
        cudaFuncSetAttribute(moe_down, cudaFuncAttributeMaxDynamicSharedMemorySize, DN_SMEM);
        attr_done = true;
    }

    {
        dim3 grid(HIDDEN / 64, TOK_PER_E / 128, NUM_EXPERTS);  // (16, 2, 64)
        moe_gateup<<<grid, NTHREADS, GU_SMEM>>>(x, w1, w3, h);
    }
    {
        dim3 grid(DIM / 128, TOK_PER_E / 128, NUM_EXPERTS);    // (16, 2, 64)
        moe_down<<<grid, NTHREADS, DN_SMEM>>>(h, w2, out);
    }
}

// round 7
// speedup vs baseline: 1.3398x; 1.1085x over previous
#include <cuda_runtime.h>
#include <cuda_bf16.h>
#include <cstdint>

// ---------------- problem constants ----------------
#define NUM_EXPERTS 64
#define DIM 2048
#define HIDDEN 1024
#define TOK_PER_E 256
#define TOTAL_TOKENS (NUM_EXPERTS * TOK_PER_E)

#define NTHREADS 256

// scratch: packed tf32-rounded h (64 MB) and packed x (128 MB)
__device__ float g_hp[(size_t)TOTAL_TOKENS * HIDDEN];
__device__ float g_xp[(size_t)TOTAL_TOKENS * DIM];

// ---------------- smem layout ----------------
// A stage (packed fragments): 128 rows x 32 k = 16384 B, 3-stage ring
#define A_PK 16384
#define B64_PITCH_W 72
#define B64_BYTES (32 * B64_PITCH_W * 4)       // 9216
#define B128_PITCH_W 136
#define B128_BYTES (32 * B128_PITCH_W * 4)     // 17408

#define GU_B_BASE (3 * A_PK)                   // 49152
#define GU_B_STAGE (2 * B64_BYTES)             // 18432
#define GU_SMEM (GU_B_BASE + 2 * GU_B_STAGE)   // 86016
#define DN_B_BASE (3 * A_PK)
#define DN_SMEM (DN_B_BASE + 2 * B128_BYTES)   // 83968

// ---------------- PTX helpers ----------------
__device__ __forceinline__ uint32_t smem_u32(const void* p) {
    uint32_t a;
    asm("{ .reg .u64 t; cvta.to.shared.u64 t, %1; cvt.u32.u64 %0, t; }" : "=r"(a) : "l"(p));
    return a;
}
__device__ __forceinline__ uint32_t tf32r(float v) {
    uint32_t o; asm("cvt.rna.tf32.f32 %0, %1;" : "=r"(o) : "f"(v)); return o;
}
__device__ __forceinline__ void cp_async16(uint32_t dst, const void* src) {
    asm volatile("cp.async.cg.shared.global [%0], [%1], 16;" :: "r"(dst), "l"(src));
}
__device__ __forceinline__ void cp_commit() {
    asm volatile("cp.async.commit_group;" ::: "memory");
}
template <int N>
__device__ __forceinline__ void cp_wait() {
    asm volatile("cp.async.wait_group %0;" :: "n"(N) : "memory");
}
__device__ __forceinline__ void mma_tf32(float d[4], const uint32_t a[4],
                                         uint32_t b0, uint32_t b1) {
    asm volatile(
        "mma.sync.aligned.m16n8k8.row.col.f32.tf32.tf32.f32 "
        "{%0,%1,%2,%3}, {%4,%5,%6,%7}, {%8,%9}, {%0,%1,%2,%3};"
        : "+f"(d[0]), "+f"(d[1]), "+f"(d[2]), "+f"(d[3])
        : "r"(a[0]), "r"(a[1]), "r"(a[2]), "r"(a[3]), "r"(b0), "r"(b1));
}
__device__ __forceinline__ float4 cvt4(float4 v) {
    v.x = __uint_as_float(tf32r(v.x));
    v.y = __uint_as_float(tf32r(v.y));
    v.z = __uint_as_float(tf32r(v.z));
    v.w = __uint_as_float(tf32r(v.w));
    return v;
}

// ================= x pre-pass: round to tf32 + fragment-pack =================
// per (e, mt, it): 32 frags (mt16 0..7 x s 0..3) x 32 lanes x float4
// lane(g,c): {x[mt16*16+g][8s+c], x[g+8][8s+c], x[g][8s+c+4], x[g+8][8s+c+4]}
__global__ void xpack_kernel(const float* __restrict__ x, float* __restrict__ xp)
{
    const int it = blockIdx.x, mt = blockIdx.y, e = blockIdx.z, tid = threadIdx.x;
    const float* src = x + ((long long)e * TOK_PER_E + mt * 128) * DIM + it * 32;
    float4* dst = (float4*)(xp + ((long long)(e * 2 + mt) * 64 + it) * 4096);
#pragma unroll
    for (int j = 0; j < 4; j++) {
        int fl = tid + 256 * j;
        int fA = fl >> 5, lane = fl & 31;
        int mt16 = fA >> 2, s = fA & 3, g = lane >> 2, c = lane & 3;
        const float* p = src + (long long)(mt16 * 16 + g) * DIM + s * 8 + c;
        float4 v;
        v.x = __uint_as_float(tf32r(p[0]));
        v.y = __uint_as_float(tf32r(p[8 * DIM]));
        v.z = __uint_as_float(tf32r(p[4]));
        v.w = __uint_as_float(tf32r(p[8 * DIM + 4]));
        dst[fl] = v;
    }
}

// ================= fused gate/up + SiLU =================
// BM=128, BN=64 per matrix, BK=32. 8 warps: wm(4) x wn(2), warp tile 32x32 per matrix.
__global__ __launch_bounds__(NTHREADS, 2)
void moe_gateup(const float* __restrict__ xp, const float* __restrict__ w1,
                const float* __restrict__ w3, float* __restrict__ hp)
{
    extern __shared__ char smem[];
    const int tid = threadIdx.x, lane = tid & 31, wid = tid >> 5;
    const int wm = wid >> 1, wn = wid & 1;
    const int e = blockIdx.z, mt = blockIdx.y, nt = blockIdx.x;

    const float4* xpe = (const float4*)(xp + (long long)(e * 2 + mt) * 64 * 4096);
    const float* w1e = w1 + (long long)e * DIM * HIDDEN + nt * 64;
    const float* w3e = w3 + (long long)e * DIM * HIDDEN + nt * 64;

    float4 v1[2], v3[2];  // B staging registers

    auto ldgB = [&](int kt) {
#pragma unroll
        for (int j = 0; j < 2; j++) {
            int id = tid + 256 * j;
            int k = id >> 4, c4 = id & 15;
            v1[j] = *(const float4*)(w1e + (long long)(kt + k) * HIDDEN + c4 * 4);
            v3[j] = *(const float4*)(w3e + (long long)(kt + k) * HIDDEN + c4 * 4);
        }
    };
    auto stsB = [&](int buf) {
        char* base = smem + GU_B_BASE + buf * GU_B_STAGE;
#pragma unroll
        for (int j = 0; j < 2; j++) {
            int id = tid + 256 * j;
            int k = id >> 4, c4 = id & 15;
            *(float4*)(base + k * 288 + c4 * 16) = cvt4(v1[j]);
            *(float4*)(base + B64_BYTES + k * 288 + c4 * 16) = cvt4(v3[j]);
        }
    };
    auto ldA = [&](int stage, int buf) {
        uint32_t sA = smem_u32(smem) + buf * A_PK;
        const float4* src = xpe + (long long)stage * 1024;
#pragma unroll
        for (int j = 0; j < 4; j++) {
            int idx = tid + 256 * j;
            cp_async16(sA + idx * 16, src + idx);
        }
        cp_commit();
    };

    float accG[2][4][4] = {}, accU[2][4][4] = {};

    // prologue
    ldgB(0);
    ldA(0, 0);
    ldA(1, 1);
    stsB(0);
    ldgB(32);
    cp_wait<1>();
    __syncthreads();

    const int NIT = DIM / 32;  // 64
    int a3 = 0, a3n = 2;
    for (int it = 0; it < NIT; ++it) {
        const int b = it & 1;
        if (it + 2 < NIT) ldA(it + 2, a3n);

        const uint4* Ap = (const uint4*)(smem + a3 * A_PK);
        const uint32_t* B1s = (const uint32_t*)(smem + GU_B_BASE + b * GU_B_STAGE);
        const uint32_t* B3s = B1s + 32 * B64_PITCH_W;

#pragma unroll
        for (int s = 0; s < 4; s++) {
            const int k0 = 8 * s + (lane & 3);
            uint32_t a[2][4];
            {
                uint4 t0 = Ap[((2 * wm + 0) * 4 + s) * 32 + lane];
                uint4 t1 = Ap[((2 * wm + 1) * 4 + s) * 32 + lane];
                a[0][0] = t0.x; a[0][1] = t0.y; a[0][2] = t0.z; a[0][3] = t0.w;
                a[1][0] = t1.x; a[1][1] = t1.y; a[1][2] = t1.z; a[1][3] = t1.w;
            }
#pragma unroll
            for (int ni = 0; ni < 4; ni++) {
                const int nb = wn * 32 + ni * 8 + (lane >> 2);
                {
                    const uint32_t* bp = B1s + k0 * B64_PITCH_W + nb;
                    uint32_t b0 = bp[0], b1v = bp[4 * B64_PITCH_W];
                    mma_tf32(accG[0][ni], a[0], b0, b1v);
                    mma_tf32(accG[1][ni], a[1], b0, b1v);
                }
                {
                    const uint32_t* bp = B3s + k0 * B64_PITCH_W + nb;
                    uint32_t b0 = bp[0], b1v = bp[4 * B64_PITCH_W];
                    mma_tf32(accU[0][ni], a[0], b0, b1v);
                    mma_tf32(accU[1][ni], a[1], b0, b1v);
                }
            }
        }
        if (it + 1 < NIT) stsB(1 - b);
        if (it + 2 < NIT) { ldgB((it + 2) * 32); cp_wait<1>(); }
        else cp_wait<0>();
        __syncthreads();
        a3 = (a3 == 2) ? 0 : a3 + 1;
        a3n = (a3n == 2) ? 0 : a3n + 1;
    }

    // epilogue: h = silu(gate)*up, tf32-rounded, written FRAGMENT-PACKED:
    // hp[((e*16 + mtile)*128 + kc)*128 + (g*4 + nn%4)*4 + (r_hi?1:0) + (nn>=4?2:0)]
    const int g = lane >> 2, c = lane & 3;
#pragma unroll
    for (int mi = 0; mi < 2; mi++) {
        const int mtile = mt * 8 + 2 * wm + mi;
#pragma unroll
        for (int ni = 0; ni < 4; ni++) {
            const int kc = nt * 8 + wn * 4 + ni;
            float* base = hp + ((long long)(e * 16 + mtile) * 128 + kc) * 128;
#pragma unroll
            for (int j = 0; j < 4; j++) {
                float gv = accG[mi][ni][j], uv = accU[mi][ni][j];
                float val = __uint_as_float(tf32r(gv / (1.f + __expf(-gv)) * uv));
                int nn = 2 * c + (j & 1);
                int idx = (g * 4 + (nn & 3)) * 4 + ((j >> 1) & 1) + ((nn >= 4) ? 2 : 0);
                base[idx] = val;
            }
        }
    }
}

// ================= down-projection =================
// BM=128, BN=128, BK=32. Warp tile 32x64.
__global__ __launch_bounds__(NTHREADS, 2)
void moe_down(const float* __restrict__ hp, const float* __restrict__ w2,
              float* __restrict__ out)
{
    extern __shared__ char smem[];
    const int tid = threadIdx.x, lane = tid & 31, wid = tid >> 5;
    const int wm = wid >> 1, wn = wid & 1, g = lane >> 2, c = lane & 3;
    const int e = blockIdx.z, mt = blockIdx.y, nt = blockIdx.x;

    const float* hpe = hp + (long long)(e * 16 + mt * 8) * 128 * 128;
    const float* w2e = w2 + (long long)e * HIDDEN * DIM + nt * 128;

    float4 v[4];  // B staging registers

    auto ldgB = [&](int kt) {
#pragma unroll
        for (int j = 0; j < 4; j++) {
            int id = tid + 256 * j;
            int k = id >> 5, c4 = id & 31;
            v[j] = *(const float4*)(w2e + (long long)(kt + k) * DIM + c4 * 4);
        }
    };
    auto stsB = [&](int buf) {
        char* base = smem + DN_B_BASE + buf * B128_BYTES;
#pragma unroll
        for (int j = 0; j < 4; j++) {
            int id = tid + 256 * j;
            int k = id >> 5, c4 = id & 31;
            *(float4*)(base + k * 544 + c4 * 16) = cvt4(v[j]);
        }
    };
    auto ldA = [&](int stage, int buf) {
        uint32_t sA = smem_u32(smem) + buf * A_PK;
#pragma unroll
        for (int j = 0; j < 4; j++) {
            int idx = tid + 256 * j;
            int f = idx >> 5, mt16 = f >> 2, s = f & 3, ln = idx & 31;
            cp_async16(sA + idx * 16,
                       hpe + ((long long)mt16 * 128 + stage * 4 + s) * 128 + ln * 4);
        }
        cp_commit();
    };

    float acc[2][8][4] = {};

    ldgB(0);
    ldA(0, 0);
    ldA(1, 1);
    stsB(0);
    ldgB(32);
    cp_wait<1>();
    __syncthreads();

    const int NIT = HIDDEN / 32;  // 32
    int a3 = 0, a3n = 2;
    for (int it = 0; it < NIT; ++it) {
        const int b = it & 1;
        if (it + 2 < NIT) ldA(it + 2, a3n);

        const uint4* Ap = (const uint4*)(smem + a3 * A_PK);
        const uint32_t* Bs = (const uint32_t*)(smem + DN_B_BASE + b * B128_BYTES);

#pragma unroll
        for (int s = 0; s < 4; s++) {
            const int k0 = 8 * s + c;
            uint32_t a[2][4];
            {
                uint4 t0 = Ap[((2 * wm + 0) * 4 + s) * 32 + lane];
                uint4 t1 = Ap[((2 * wm + 1) * 4 + s) * 32 + lane];
                a[0][0] = t0.x; a[0][1] = t0.y; a[0][2] = t0.z; a[0][3] = t0.w;
                a[1][0] = t1.x; a[1][1] = t1.y; a[1][2] = t1.z; a[1][3] = t1.w;
            }
#pragma unroll
            for (int ni = 0; ni < 8; ni++) {
                const uint32_t* bp = Bs + k0 * B128_PITCH_W + wn * 64 + ni * 8 + g;
                uint32_t b0 = bp[0], b1v = bp[4 * B128_PITCH_W];
                mma_tf32(acc[0][ni], a[0], b0, b1v);
                mma_tf32(acc[1][ni], a[1], b0, b1v);
            }
        }
        if (it + 1 < NIT) stsB(1 - b);
        if (it + 2 < NIT) { ldgB((it + 2) * 32); cp_wait<1>(); }
        else cp_wait<0>();
        __syncthreads();
        a3 = (a3 == 2) ? 0 : a3 + 1;
        a3n = (a3n == 2) ? 0 : a3n + 1;
    }

    const int colbase = nt * 128 + wn * 64;
    const long long rowbase = (long long)e * TOK_PER_E + mt * 128 + wm * 32;
#pragma unroll
    for (int mi = 0; mi < 2; mi++) {
        const long long r0 = rowbase + mi * 16 + g;
#pragma unroll
        for (int ni = 0; ni < 8; ni++) {
            const int col = colbase + ni * 8 + 2 * c;
            float* p0 = out + r0 * DIM + col;
            float* p1 = p0 + 8 * DIM;
            *(float2*)p0 = make_float2(acc[mi][ni][0], acc[mi][ni][1]);
            *(float2*)p1 = make_float2(acc[mi][ni][2], acc[mi][ni][3]);
        }
    }
}

// ================= launch =================
extern "C" void kernel_launch(void* const* d_in, const int* in_sizes, int n_in,
                              void* d_out, int out_size)
{
    const float* x  = (const float*)d_in[0];
    const float* w1 = (const float*)d_in[1];
    const float* w2 = (const float*)d_in[2];
    const float* w3 = (const float*)d_in[3];
    float* out = (float*)d_out;

    float* hp = nullptr;
    float* xp = nullptr;
    cudaGetSymbolAddress((void**)&hp, g_hp);
    cudaGetSymbolAddress((void**)&xp, g_xp);

    static bool attr_done = false;
    if (!attr_done) {
        cudaFuncSetAttribute(moe_gateup, cudaFuncAttributeMaxDynamicSharedMemorySize, GU_SMEM);
        cudaFuncSetAttribute(moe_down, cudaFuncAttributeMaxDynamicSharedMemorySize, DN_SMEM);
        attr_done = true;
    }

    {
        dim3 grid(DIM / 32, TOK_PER_E / 128, NUM_EXPERTS);     // (64, 2, 64)
        xpack_kernel<<<grid, NTHREADS>>>(x, xp);
    }
    {
        dim3 grid(HIDDEN / 64, TOK_PER_E / 128, NUM_EXPERTS);  // (16, 2, 64)
        moe_gateup<<<grid, NTHREADS, GU_SMEM>>>(xp, w1, w3, hp);
    }
    {
        dim3 grid(DIM / 128, TOK_PER_E / 128, NUM_EXPERTS);    // (16, 2, 64)
        moe_down<<<grid, NTHREADS, DN_SMEM>>>(hp, w2, out);
    }
}

// round 8
// speedup vs baseline: 1.7771x; 1.3264x over previous
#include <cuda_runtime.h>
#include <cuda_fp16.h>
#include <cstdint>

// ---------------- problem constants ----------------
#define NUM_EXPERTS 64
#define DIM 2048
#define HIDDEN 1024
#define TOK_PER_E 256
#define TOTAL_TOKENS (NUM_EXPERTS * TOK_PER_E)
#define NTHREADS 256

// scratch: fp16 fragment-packed x (64MB) and h (32MB)
__device__ uint4 g_xp[(size_t)TOTAL_TOKENS * DIM / 8];
__device__ uint4 g_hp[(size_t)TOTAL_TOKENS * HIDDEN / 8];

// ---------------- smem layout ----------------
// A stage: 128 rows x 64 k fp16 fragment-packed = 16384 B, 3-stage ring
// gateup B stage: w1 8KB + w3 8KB = 16384 B, 2-stage
// down  B stage: 16KB, 2-stage
#define A_PK 16384
#define B_BASE (3 * A_PK)                // 49152
#define SMEM_TOT (B_BASE + 2 * 16384)    // 81920 (both kernels)

// ---------------- helpers ----------------
__device__ __forceinline__ uint32_t smem_u32(const void* p) {
    uint32_t a;
    asm("{ .reg .u64 t; cvta.to.shared.u64 t, %1; cvt.u32.u64 %0, t; }" : "=r"(a) : "l"(p));
    return a;
}
__device__ __forceinline__ void cp_async16(uint32_t dst, const void* src) {
    asm volatile("cp.async.cg.shared.global [%0], [%1], 16;" :: "r"(dst), "l"(src));
}
__device__ __forceinline__ void cp_commit() {
    asm volatile("cp.async.commit_group;" ::: "memory");
}
template <int N>
__device__ __forceinline__ void cp_wait() {
    asm volatile("cp.async.wait_group %0;" :: "n"(N) : "memory");
}
__device__ __forceinline__ void mma_f16(float d[4], const uint32_t a[4],
                                        uint32_t b0, uint32_t b1) {
    asm volatile(
        "mma.sync.aligned.m16n8k16.row.col.f32.f16.f16.f32 "
        "{%0,%1,%2,%3}, {%4,%5,%6,%7}, {%8,%9}, {%0,%1,%2,%3};"
        : "+f"(d[0]), "+f"(d[1]), "+f"(d[2]), "+f"(d[3])
        : "r"(a[0]), "r"(a[1]), "r"(a[2]), "r"(a[3]), "r"(b0), "r"(b1));
}
__device__ __forceinline__ uint32_t packh2(float lo, float hi) {
    __half2 h = __floats2half2_rn(lo, hi);
    return *(uint32_t*)&h;
}
// B fragment word address (word units). lw = lane'*2 + slot (0..63).
__device__ __forceinline__ uint32_t bword(uint32_t f, uint32_t lw) {
    uint32_t swz = (((f >> 2) & 7) << 2) ^ (((f >> 5) & 1) << 1);
    return f * 64 + (lw ^ swz);
}
__device__ __forceinline__ void lds64(uint32_t& r0, uint32_t& r1, uint32_t addr) {
    asm volatile("ld.shared.v2.b32 {%0,%1}, [%2];" : "=r"(r0), "=r"(r1) : "r"(addr));
}

// ================= x pre-pass: fp32 -> fp16 fragment-packed =================
// per (e, mt, it64): 32 frags (mt16 0..7 x s 0..3) x 32 lanes x uint4
// lane(g,c): {h2(A[g][16s+2c],+1), h2(A[g+8][..]), h2(A[g][2c+8],+1), h2(A[g+8][2c+8],+1)}
__global__ void xpack_kernel(const float* __restrict__ x, uint4* __restrict__ xp)
{
    const int it = blockIdx.x, mt = blockIdx.y, e = blockIdx.z, tid = threadIdx.x;
    const float* src = x + ((long long)e * TOK_PER_E + mt * 128) * DIM + it * 64;
    uint4* dst = xp + ((long long)(e * 2 + mt) * 32 + it) * 1024;
#pragma unroll
    for (int j = 0; j < 4; j++) {
        int fl = tid + 256 * j;
        int fA = fl >> 5, lane = fl & 31;
        int mt16 = fA >> 2, s = fA & 3, g = lane >> 2, c = lane & 3;
        const float* p = src + (long long)(mt16 * 16 + g) * DIM + s * 16 + 2 * c;
        float2 q0 = *(const float2*)p;
        float2 q1 = *(const float2*)(p + 8 * DIM);
        float2 q2 = *(const float2*)(p + 8);
        float2 q3 = *(const float2*)(p + 8 * DIM + 8);
        uint4 v;
        v.x = packh2(q0.x, q0.y);
        v.y = packh2(q1.x, q1.y);
        v.z = packh2(q2.x, q2.y);
        v.w = packh2(q3.x, q3.y);
        dst[fl] = v;
    }
}

// ================= fused gate/up + SiLU =================
// BM=128, BN=64 per matrix, BK=64. 8 warps: wm(4) x wn(2), warp tile 32x32 per matrix.
__global__ __launch_bounds__(NTHREADS, 2)
void moe_gateup(const uint4* __restrict__ xp, const float* __restrict__ w1,
                const float* __restrict__ w3, uint4* __restrict__ hp)
{
    extern __shared__ char smem[];
    const int tid = threadIdx.x, lane = tid & 31, wid = tid >> 5;
    const int wm = wid >> 1, wn = wid & 1, g = lane >> 2, c = lane & 3;
    const int e = blockIdx.z, mt = blockIdx.y, nt = blockIdx.x;

    const uint4* xpe = xp + (long long)(e * 2 + mt) * 32 * 1024;
    const float* w1e = w1 + (long long)e * DIM * HIDDEN + nt * 64;
    const float* w3e = w3 + (long long)e * DIM * HIDDEN + nt * 64;

    uint32_t s1[8], s3[8];  // staged half2 words (2 passes x 4)

    auto ldgB = [&](int kt) {
#pragma unroll
        for (int j = 0; j < 2; j++) {
            int id = tid + 256 * j;
            int m = id >> 4, c4 = id & 15;
            const float* p1 = w1e + (long long)(kt + 2 * m) * HIDDEN + 4 * c4;
            float4 r0 = *(const float4*)p1;
            float4 r1 = *(const float4*)(p1 + HIDDEN);
            s1[j * 4 + 0] = packh2(r0.x, r1.x);
            s1[j * 4 + 1] = packh2(r0.y, r1.y);
            s1[j * 4 + 2] = packh2(r0.z, r1.z);
            s1[j * 4 + 3] = packh2(r0.w, r1.w);
            const float* p3 = w3e + (long long)(kt + 2 * m) * HIDDEN + 4 * c4;
            float4 t0 = *(const float4*)p3;
            float4 t1 = *(const float4*)(p3 + HIDDEN);
            s3[j * 4 + 0] = packh2(t0.x, t1.x);
            s3[j * 4 + 1] = packh2(t0.y, t1.y);
            s3[j * 4 + 2] = packh2(t0.z, t1.z);
            s3[j * 4 + 3] = packh2(t0.w, t1.w);
        }
    };
    auto stsB = [&](int buf) {
        uint32_t* b1 = (uint32_t*)(smem + B_BASE + buf * 16384);
        uint32_t* b3 = b1 + 2048;
#pragma unroll
        for (int j = 0; j < 2; j++) {
            int id = tid + 256 * j;
            int m = id >> 4, c4 = id & 15;
            uint32_t f = (uint32_t)(c4 >> 1) * 4 + (m >> 3);
            uint32_t slot = (m >> 2) & 1;
#pragma unroll
            for (int i = 0; i < 4; i++) {
                uint32_t lp = (uint32_t)(4 * (c4 & 1) + i) * 4 + (m & 3);
                uint32_t w = bword(f, lp * 2 + slot);
                b1[w] = s1[j * 4 + i];
                b3[w] = s3[j * 4 + i];
            }
        }
    };
    auto ldA = [&](int stage, int buf) {
        uint32_t sA = smem_u32(smem) + buf * A_PK;
        const uint4* src = xpe + (long long)stage * 1024;
#pragma unroll
        for (int j = 0; j < 4; j++) {
            int idx = tid + 256 * j;
            cp_async16(sA + idx * 16, src + idx);
        }
        cp_commit();
    };

    float accG[2][4][4] = {}, accU[2][4][4] = {};

    ldgB(0);
    ldA(0, 0);
    ldA(1, 1);
    stsB(0);
    ldgB(64);
    cp_wait<1>();
    __syncthreads();

    const int NIT = DIM / 64;  // 32
    int a3 = 0, a3n = 2;
    for (int it = 0; it < NIT; ++it) {
        const int b = it & 1;
        if (it + 2 < NIT) ldA(it + 2, a3n);

        const uint4* Ap = (const uint4*)(smem + a3 * A_PK);
        const uint32_t B1base = smem_u32(smem) + B_BASE + b * 16384;
        const uint32_t B3base = B1base + 8192;

#pragma unroll
        for (int s = 0; s < 4; s++) {
            uint32_t a[2][4];
            {
                uint4 t0 = Ap[((2 * wm + 0) * 4 + s) * 32 + lane];
                uint4 t1 = Ap[((2 * wm + 1) * 4 + s) * 32 + lane];
                a[0][0] = t0.x; a[0][1] = t0.y; a[0][2] = t0.z; a[0][3] = t0.w;
                a[1][0] = t1.x; a[1][1] = t1.y; a[1][2] = t1.z; a[1][3] = t1.w;
            }
#pragma unroll
            for (int ni = 0; ni < 4; ni++) {
                uint32_t f = (uint32_t)(wn * 4 + ni) * 4 + s;
                uint32_t woff = bword(f, (uint32_t)lane * 2) * 4;
                uint32_t b0, b1v;
                lds64(b0, b1v, B1base + woff);
                mma_f16(accG[0][ni], a[0], b0, b1v);
                mma_f16(accG[1][ni], a[1], b0, b1v);
                uint32_t c0, c1v;
                lds64(c0, c1v, B3base + woff);
                mma_f16(accU[0][ni], a[0], c0, c1v);
                mma_f16(accU[1][ni], a[1], c0, c1v);
            }
        }
        if (it + 1 < NIT) stsB(1 - b);
        if (it + 2 < NIT) { ldgB((it + 2) * 64); cp_wait<1>(); }
        else cp_wait<0>();
        __syncthreads();
        a3 = (a3 == 2) ? 0 : a3 + 1;
        a3n = (a3n == 2) ? 0 : a3n + 1;
    }

    // epilogue: h = silu(gate)*up -> fp16, fragment-packed, coalesced uint4 stores
    uint4* hpe = hp + ((long long)(e * 2 + mt) * 16 + nt) * 1024;
#pragma unroll
    for (int mi = 0; mi < 2; mi++) {
#pragma unroll
        for (int nip = 0; nip < 2; nip++) {
            float hv[2][4];
#pragma unroll
            for (int q = 0; q < 2; q++) {
                int ni = 2 * nip + q;
#pragma unroll
                for (int j = 0; j < 4; j++) {
                    float gv = accG[mi][ni][j], uv = accU[mi][ni][j];
                    hv[q][j] = gv / (1.f + __expf(-gv)) * uv;
                }
            }
            uint4 v;
            v.x = packh2(hv[0][0], hv[0][1]);
            v.y = packh2(hv[0][2], hv[0][3]);
            v.z = packh2(hv[1][0], hv[1][1]);
            v.w = packh2(hv[1][2], hv[1][3]);
            int f_dn = (wm * 2 + mi) * 4 + (wn * 2 + nip);
            hpe[f_dn * 32 + lane] = v;
        }
    }
}

// ================= down-projection =================
// BM=128, BN=128, BK=64. Warp tile 32x64.
__global__ __launch_bounds__(NTHREADS, 2)
void moe_down(const uint4* __restrict__ hp, const float* __restrict__ w2,
              float* __restrict__ out)
{
    extern __shared__ char smem[];
    const int tid = threadIdx.x, lane = tid & 31, wid = tid >> 5;
    const int wm = wid >> 1, wn = wid & 1, g = lane >> 2, c = lane & 3;
    const int e = blockIdx.z, mt = blockIdx.y, nt = blockIdx.x;

    const uint4* hpe = hp + (long long)(e * 2 + mt) * 16 * 1024;
    const float* w2e = w2 + (long long)e * HIDDEN * DIM + nt * 128;

    uint32_t sw[16];  // staged half2 words (4 passes x 4)

    auto ldgB = [&](int kt) {
#pragma unroll
        for (int j = 0; j < 4; j++) {
            int id = tid + 256 * j;
            int m = id >> 5, c4 = id & 31;
            const float* p = w2e + (long long)(kt + 2 * m) * DIM + 4 * c4;
            float4 r0 = *(const float4*)p;
            float4 r1 = *(const float4*)(p + DIM);
            sw[j * 4 + 0] = packh2(r0.x, r1.x);
            sw[j * 4 + 1] = packh2(r0.y, r1.y);
            sw[j * 4 + 2] = packh2(r0.z, r1.z);
            sw[j * 4 + 3] = packh2(r0.w, r1.w);
        }
    };
    auto stsB = [&](int buf) {
        uint32_t* bb = (uint32_t*)(smem + B_BASE + buf * 16384);
#pragma unroll
        for (int j = 0; j < 4; j++) {
            int id = tid + 256 * j;
            int m = id >> 5, c4 = id & 31;
            uint32_t f = (uint32_t)(c4 >> 1) * 4 + (m >> 3);
            uint32_t slot = (m >> 2) & 1;
#pragma unroll
            for (int i = 0; i < 4; i++) {
                uint32_t lp = (uint32_t)(4 * (c4 & 1) + i) * 4 + (m & 3);
                bb[bword(f, lp * 2 + slot)] = sw[j * 4 + i];
            }
        }
    };
    auto ldA = [&](int stage, int buf) {
        uint32_t sA = smem_u32(smem) + buf * A_PK;
        const uint4* src = hpe + (long long)stage * 1024;
#pragma unroll
        for (int j = 0; j < 4; j++) {
            int idx = tid + 256 * j;
            cp_async16(sA + idx * 16, src + idx);
        }
        cp_commit();
    };

    float acc[2][8][4] = {};

    ldgB(0);
    ldA(0, 0);
    ldA(1, 1);
    stsB(0);
    ldgB(64);
    cp_wait<1>();
    __syncthreads();

    const int NIT = HIDDEN / 64;  // 16
    int a3 = 0, a3n = 2;
    for (int it = 0; it < NIT; ++it) {
        const int b = it & 1;
        if (it + 2 < NIT) ldA(it + 2, a3n);

        const uint4* Ap = (const uint4*)(smem + a3 * A_PK);
        const uint32_t Bbase = smem_u32(smem) + B_BASE + b * 16384;

#pragma unroll
        for (int s = 0; s < 4; s++) {
            uint32_t a[2][4];
            {
                uint4 t0 = Ap[((2 * wm + 0) * 4 + s) * 32 + lane];
                uint4 t1 = Ap[((2 * wm + 1) * 4 + s) * 32 + lane];
                a[0][0] = t0.x; a[0][1] = t0.y; a[0][2] = t0.z; a[0][3] = t0.w;
                a[1][0] = t1.x; a[1][1] = t1.y; a[1][2] = t1.z; a[1][3] = t1.w;
            }
#pragma unroll
            for (int ni = 0; ni < 8; ni++) {
                uint32_t f = (uint32_t)(wn * 8 + ni) * 4 + s;
                uint32_t b0, b1v;
                lds64(b0, b1v, Bbase + bword(f, (uint32_t)lane * 2) * 4);
                mma_f16(acc[0][ni], a[0], b0, b1v);
                mma_f16(acc[1][ni], a[1], b0, b1v);
            }
        }
        if (it + 1 < NIT) stsB(1 - b);
        if (it + 2 < NIT) { ldgB((it + 2) * 64); cp_wait<1>(); }
        else cp_wait<0>();
        __syncthreads();
        a3 = (a3 == 2) ? 0 : a3 + 1;
        a3n = (a3n == 2) ? 0 : a3n + 1;
    }

    const int colbase = nt * 128 + wn * 64;
    const long long rowbase = (long long)e * TOK_PER_E + mt * 128 + wm * 32;
#pragma unroll
    for (int mi = 0; mi < 2; mi++) {
        const long long r0 = rowbase + mi * 16 + g;
#pragma unroll
        for (int ni = 0; ni < 8; ni++) {
            const int col = colbase + ni * 8 + 2 * c;
            float* p0 = out + r0 * DIM + col;
            float* p1 = p0 + 8 * DIM;
            *(float2*)p0 = make_float2(acc[mi][ni][0], acc[mi][ni][1]);
            *(float2*)p1 = make_float2(acc[mi][ni][2], acc[mi][ni][3]);
        }
    }
}

// ================= launch =================
extern "C" void kernel_launch(void* const* d_in, const int* in_sizes, int n_in,
                              void* d_out, int out_size)
{
    const float* x  = (const float*)d_in[0];
    const float* w1 = (const float*)d_in[1];
    const float* w2 = (const float*)d_in[2];
    const float* w3 = (const float*)d_in[3];
    float* out = (float*)d_out;

    uint4* xp = nullptr;
    uint4* hp = nullptr;
    cudaGetSymbolAddress((void**)&xp, g_xp);
    cudaGetSymbolAddress((void**)&hp, g_hp);

    static bool attr_done = false;
    if (!attr_done) {
        cudaFuncSetAttribute(moe_gateup, cudaFuncAttributeMaxDynamicSharedMemorySize, SMEM_TOT);
        cudaFuncSetAttribute(moe_down, cudaFuncAttributeMaxDynamicSharedMemorySize, SMEM_TOT);
        attr_done = true;
    }

    {
        dim3 grid(DIM / 64, TOK_PER_E / 128, NUM_EXPERTS);     // (32, 2, 64)
        xpack_kernel<<<grid, NTHREADS>>>(x, xp);
    }
    {
        dim3 grid(HIDDEN / 64, TOK_PER_E / 128, NUM_EXPERTS);  // (16, 2, 64)
        moe_gateup<<<grid, NTHREADS, SMEM_TOT>>>(xp, w1, w3, hp);
    }
    {
        dim3 grid(DIM / 128, TOK_PER_E / 128, NUM_EXPERTS);    // (16, 2, 64)
        moe_down<<<grid, NTHREADS, SMEM_TOT>>>(hp, w2, out);
    }
}